// round 2
// baseline (speedup 1.0000x reference)
#include <cuda_runtime.h>
#include <cuda_bf16.h>
#include <math.h>

// ---------------- Problem constants ----------------
#define VOCAB 32000
#define DMODEL 1024
#define DEPTH 6
#define NHEAD 16
#define SEQL 1024
#define BATCH 2
#define LRANK 16
#define HIDDEN 4096
#define HEADDIM 64
#define NTOK (BATCH * SEQL)          // 2048
#define SCALING 0.5f                  // 8.0 / 16

// ---------------- Scratch (device globals; no allocation allowed) -------------
static __device__ float g_x [NTOK * DMODEL];
static __device__ float g_h [NTOK * DMODEL];
static __device__ float g_q [NTOK * DMODEL];
static __device__ float g_k [NTOK * DMODEL];
static __device__ float g_v [NTOK * DMODEL];
static __device__ float g_o [NTOK * DMODEL];
static __device__ float g_ff[NTOK * HIDDEN];
static __device__ float g_scores[(long)BATCH * NHEAD * SEQL * SEQL]; // 128 MB
static __device__ float g_wq[DEPTH * DMODEL * DMODEL];
static __device__ float g_wk[DEPTH * DMODEL * DMODEL];
static __device__ float g_wv[DEPTH * DMODEL * DMODEL];
static __device__ float g_wo[DEPTH * DMODEL * DMODEL];

// ---------------- helpers ----------------
__device__ __forceinline__ float gelu_exact(float x) {
    return 0.5f * x * (1.0f + erff(x * 0.70710678118654752440f));
}

// ---------------- W_eff = W + 0.5 * A @ B  (LoRA fold) ----------------
__global__ void weff_kernel(const float* __restrict__ W,
                            const float* __restrict__ Am,   // [DEPTH, D, R]
                            const float* __restrict__ Bm,   // [DEPTH, R, D]
                            float* __restrict__ out) {
    long e = (long)blockIdx.x * 256 + threadIdx.x;          // DEPTH*D*D total
    int layer = (int)(e / (DMODEL * DMODEL));
    int rem   = (int)(e % (DMODEL * DMODEL));
    int orow  = rem / DMODEL;
    int icol  = rem % DMODEL;
    const float* a  = Am + (long)layer * DMODEL * LRANK + (long)orow * LRANK;
    const float* bb = Bm + (long)layer * LRANK * DMODEL + icol;
    float s = 0.0f;
#pragma unroll
    for (int r = 0; r < LRANK; r++) s += a[r] * bb[(long)r * DMODEL];
    out[e] = W[e] + SCALING * s;
}

// ---------------- Embedding + phase rotator ----------------
__global__ void embed_kernel(const int* __restrict__ idx,
                             const float* __restrict__ tok,
                             const float* __restrict__ pos,
                             const float* __restrict__ phase,
                             float* __restrict__ x) {
    int row = blockIdx.x;                 // 0..NTOK-1
    int l   = row % SEQL;
    int t   = idx[row];
    for (int d = threadIdx.x; d < DMODEL; d += blockDim.x) {
        float phi = tanhf(phase[d]) * 3.14159265358979323846f;
        float fac = cosf(phi) - sinf(phi);
        x[(long)row * DMODEL + d] =
            (tok[(long)t * DMODEL + d] + pos[(long)l * DMODEL + d]) * fac;
    }
}

// ---------------- LayerNorm (row per block, D=1024, 256 threads) ------------
__global__ void ln_kernel(const float* __restrict__ x,
                          const float* __restrict__ w,
                          const float* __restrict__ b,
                          float* __restrict__ o) {
    int row = blockIdx.x;
    const float* xr = x + (long)row * DMODEL;
    int tid = threadIdx.x;
    float s = 0.f, s2 = 0.f;
    float v[4];
#pragma unroll
    for (int j = 0; j < 4; j++) {
        v[j] = xr[tid + 256 * j];
        s += v[j]; s2 += v[j] * v[j];
    }
    __shared__ float r1[256], r2[256];
    r1[tid] = s; r2[tid] = s2;
    __syncthreads();
    for (int off = 128; off > 0; off >>= 1) {
        if (tid < off) { r1[tid] += r1[tid + off]; r2[tid] += r2[tid + off]; }
        __syncthreads();
    }
    float mean = r1[0] * (1.0f / DMODEL);
    float var  = r2[0] * (1.0f / DMODEL) - mean * mean;
    float rstd = rsqrtf(var + 1e-5f);
    float* orow = o + (long)row * DMODEL;
#pragma unroll
    for (int j = 0; j < 4; j++) {
        int d = tid + 256 * j;
        orow[d] = (v[j] - mean) * rstd * w[d] + b[d];
    }
}

// ---------------- Causal softmax over scores rows ----------------
// scores layout: [B*H, L, L]; row = blockIdx.x in [0, B*H*L); query pos l = row % L
__global__ void softmax_kernel(float* __restrict__ sc) {
    long row = blockIdx.x;
    int l = (int)(row % SEQL);
    float* s = sc + row * (long)SEQL;
    int tid = threadIdx.x;
    __shared__ float red[256];

    const float scale = 0.125f;   // HEADDIM^-0.5
    float mx = -3.4e38f;
    for (int j = tid; j <= l; j += 256) mx = fmaxf(mx, s[j]);
    red[tid] = mx;
    __syncthreads();
    for (int off = 128; off > 0; off >>= 1) {
        if (tid < off) red[tid] = fmaxf(red[tid], red[tid + off]);
        __syncthreads();
    }
    mx = red[0] * scale;
    __syncthreads();

    float sum = 0.f;
    for (int j = tid; j <= l; j += 256) {
        float e = __expf(s[j] * scale - mx);
        s[j] = e;
        sum += e;
    }
    red[tid] = sum;
    __syncthreads();
    for (int off = 128; off > 0; off >>= 1) {
        if (tid < off) red[tid] += red[tid + off];
        __syncthreads();
    }
    float inv = 1.0f / red[0];
    for (int j = tid; j <= l; j += 256) s[j] *= inv;
    for (int j = l + 1 + tid; j < SEQL; j += 256) s[j] = 0.0f;   // zero masked part
}

// ---------------- Generic tiled GEMM ----------------
// C[m,n] = sum_k A[m*lda+k] * B[n*sBn + k*sBk]  (+bias)(gelu)(+residual)
// flags: 1 = gelu, 4 = causal tile-skip (scores), 8 = causal K-limit (attn@V)
// batchH>0 enables batching with (outer,inner) offsets split by batchH.
template<int BM, int BN, int BK, int TM, int TN>
__global__ __launch_bounds__((BM / TM) * (BN / TN))
void gemm_kernel(const float* __restrict__ A, int lda,
                 const float* __restrict__ Bp, int sBn, int sBk,
                 const float* __restrict__ bias,
                 const float* __restrict__ res, int ldr,
                 float* __restrict__ C, int ldc,
                 int M, int N, int K, int flags,
                 int batchH,
                 long aO, long aI, long bO, long bI, long cO, long cI) {
    constexpr int THREADS = (BM / TM) * (BN / TN);
    if (batchH > 0) {
        int z = blockIdx.z;
        A  += (z / batchH) * aO + (z % batchH) * aI;
        Bp += (z / batchH) * bO + (z % batchH) * bI;
        C  += (z / batchH) * cO + (z % batchH) * cI;
    }
    int bm0 = blockIdx.y * BM;
    int bn0 = blockIdx.x * BN;
    if (flags & 4) { if (bn0 > bm0 + BM - 1) return; }     // fully above diagonal
    int Keff = K;
    if (flags & 8) Keff = min(K, bm0 + BM);                 // attn rows zero beyond m

    __shared__ float As[BK][BM + 4];
    __shared__ float Bs[BK][BN + 4];

    int tid = threadIdx.x;
    int tx = tid % (BN / TN);
    int ty = tid / (BN / TN);

    float acc[TM][TN];
#pragma unroll
    for (int i = 0; i < TM; i++)
#pragma unroll
        for (int j = 0; j < TN; j++) acc[i][j] = 0.0f;

    constexpr int A_F4 = BM * BK / 4;
    constexpr int A_PER = A_F4 / THREADS;
    constexpr int B_F4 = BN * BK / 4;
    constexpr int B_PER = (B_F4 + THREADS - 1) / THREADS;

    const bool bKcontig = (sBk == 1);

    for (int k0 = 0; k0 < Keff; k0 += BK) {
        // --- load A tile (k-contiguous in gmem), transposed into As[k][m]
#pragma unroll
        for (int t = 0; t < A_PER; t++) {
            int v = tid + t * THREADS;
            int m = v / (BK / 4);
            int kq = v % (BK / 4);
            float4 f = *reinterpret_cast<const float4*>(
                A + (long)(bm0 + m) * lda + k0 + kq * 4);
            As[kq * 4 + 0][m] = f.x;
            As[kq * 4 + 1][m] = f.y;
            As[kq * 4 + 2][m] = f.z;
            As[kq * 4 + 3][m] = f.w;
        }
        // --- load B tile
        if (bKcontig) {
#pragma unroll
            for (int t = 0; t < B_PER; t++) {
                int v = tid + t * THREADS;
                if (v < B_F4) {
                    int n = v / (BK / 4);
                    int kq = v % (BK / 4);
                    float4 f = *reinterpret_cast<const float4*>(
                        Bp + (long)(bn0 + n) * sBn + k0 + kq * 4);
                    Bs[kq * 4 + 0][n] = f.x;
                    Bs[kq * 4 + 1][n] = f.y;
                    Bs[kq * 4 + 2][n] = f.z;
                    Bs[kq * 4 + 3][n] = f.w;
                }
            }
        } else {
            // n-contiguous (sBn == 1): Bs[k][n] = Bp[(k0+k)*sBk + bn0 + n]
#pragma unroll
            for (int t = 0; t < B_PER; t++) {
                int v = tid + t * THREADS;
                if (v < B_F4) {
                    int kk = v / (BN / 4);
                    int nq = v % (BN / 4);
                    float4 f = *reinterpret_cast<const float4*>(
                        Bp + (long)(k0 + kk) * sBk + bn0 + nq * 4);
                    *reinterpret_cast<float4*>(&Bs[kk][nq * 4]) = f;
                }
            }
        }
        __syncthreads();

#pragma unroll
        for (int kk = 0; kk < BK; kk++) {
            float a[TM], b[TN];
#pragma unroll
            for (int i = 0; i < TM; i++) a[i] = As[kk][ty * TM + i];
#pragma unroll
            for (int j = 0; j < TN; j++) b[j] = Bs[kk][tx * TN + j];
#pragma unroll
            for (int i = 0; i < TM; i++)
#pragma unroll
                for (int j = 0; j < TN; j++)
                    acc[i][j] = fmaf(a[i], b[j], acc[i][j]);
        }
        __syncthreads();
    }

    // --- epilogue
#pragma unroll
    for (int i = 0; i < TM; i++) {
        int m = bm0 + ty * TM + i;
#pragma unroll
        for (int j = 0; j < TN; j++) {
            int n = bn0 + tx * TN + j;
            float c = acc[i][j];
            if (bias) c += bias[n];
            if (flags & 1) c = gelu_exact(c);
            if (res) c += res[(long)m * ldr + n];
            C[(long)m * ldc + n] = c;
        }
    }
}

// ---------------- host-side launch helpers ----------------
static void gemm128(const float* A, int lda, const float* B, int sBn, int sBk,
                    const float* bias, const float* res, int ldr,
                    float* C, int ldc, int M, int N, int K, int flags,
                    int batch = 1, int batchH = 0,
                    long aO = 0, long aI = 0, long bO = 0, long bI = 0,
                    long cO = 0, long cI = 0) {
    dim3 g(N / 128, M / 128, batch);
    gemm_kernel<128, 128, 16, 8, 8><<<g, 256>>>(
        A, lda, B, sBn, sBk, bias, res, ldr, C, ldc, M, N, K, flags,
        batchH, aO, aI, bO, bI, cO, cI);
}

static void gemm64(const float* A, int lda, const float* B, int sBn, int sBk,
                   const float* bias, const float* res, int ldr,
                   float* C, int ldc, int M, int N, int K, int flags,
                   int batch = 1, int batchH = 0,
                   long aO = 0, long aI = 0, long bO = 0, long bI = 0,
                   long cO = 0, long cI = 0) {
    dim3 g(N / 64, M / 128, batch);
    gemm_kernel<128, 64, 16, 8, 4><<<g, 256>>>(
        A, lda, B, sBn, sBk, bias, res, ldr, C, ldc, M, N, K, flags,
        batchH, aO, aI, bO, bI, cO, cI);
}

// ---------------- entry point ----------------
extern "C" void kernel_launch(void* const* d_in, const int* in_sizes, int n_in,
                              void* d_out, int out_size) {
    // Input order follows setup_inputs() dict-insertion order:
    //   0 idx, 1 tok_embed, 2 pos_embed, 3 phase,
    //   4 ln1_w, 5 ln1_b, 6 ln2_w, 7 ln2_b,
    //   8..11  Wq bq Bq Aq, 12..15 Wk bk Bk Ak,
    //   16..19 Wv bv Bv Av, 20..23 Wo bo Bo Ao,
    //   24 W1, 25 b1, 26 W2, 27 b2, 28 lnf_w, 29 lnf_b, 30 head_W
    // Defensive: if in_sizes[6] is a full weight (D*D per layer) we are in
    // reference-signature order instead (ln2 after attention block).
    const int*   idx   = (const int*)  d_in[0];
    const float* tok   = (const float*)d_in[1];
    const float* pos   = (const float*)d_in[2];
    const float* phase = (const float*)d_in[3];
    const float* ln1w  = (const float*)d_in[4];
    const float* ln1b  = (const float*)d_in[5];

    const float *ln2w, *ln2b;
    int wbase;
    if (in_sizes[6] == DEPTH * DMODEL) {        // dict order: ln2 at 6,7
        ln2w = (const float*)d_in[6];
        ln2b = (const float*)d_in[7];
        wbase = 8;
    } else {                                     // signature order: ln2 at 22,23
        ln2w = (const float*)d_in[22];
        ln2b = (const float*)d_in[23];
        wbase = 6;
    }
    const float* Wq = (const float*)d_in[wbase + 0];
    const float* bq = (const float*)d_in[wbase + 1];
    const float* Bq = (const float*)d_in[wbase + 2];
    const float* Aq = (const float*)d_in[wbase + 3];
    const float* Wk = (const float*)d_in[wbase + 4];
    const float* bk = (const float*)d_in[wbase + 5];
    const float* Bk = (const float*)d_in[wbase + 6];
    const float* Ak = (const float*)d_in[wbase + 7];
    const float* Wv = (const float*)d_in[wbase + 8];
    const float* bv = (const float*)d_in[wbase + 9];
    const float* Bv = (const float*)d_in[wbase + 10];
    const float* Av = (const float*)d_in[wbase + 11];
    const float* Wo = (const float*)d_in[wbase + 12];
    const float* bo = (const float*)d_in[wbase + 13];
    const float* Bo = (const float*)d_in[wbase + 14];
    const float* Ao = (const float*)d_in[wbase + 15];
    int mbase = (wbase == 8) ? 24 : 24;          // W1 at 24 in both orders
    const float* W1 = (const float*)d_in[mbase + 0];
    const float* b1 = (const float*)d_in[mbase + 1];
    const float* W2 = (const float*)d_in[mbase + 2];
    const float* b2 = (const float*)d_in[mbase + 3];
    const float* lnfw = (const float*)d_in[28];
    const float* lnfb = (const float*)d_in[29];
    const float* headW = (const float*)d_in[30];
    float* out = (float*)d_out;

    float *x, *h, *q, *k, *v, *o, *ff, *sc, *wq, *wk, *wv, *wo;
    cudaGetSymbolAddress((void**)&x,  g_x);
    cudaGetSymbolAddress((void**)&h,  g_h);
    cudaGetSymbolAddress((void**)&q,  g_q);
    cudaGetSymbolAddress((void**)&k,  g_k);
    cudaGetSymbolAddress((void**)&v,  g_v);
    cudaGetSymbolAddress((void**)&o,  g_o);
    cudaGetSymbolAddress((void**)&ff, g_ff);
    cudaGetSymbolAddress((void**)&sc, g_scores);
    cudaGetSymbolAddress((void**)&wq, g_wq);
    cudaGetSymbolAddress((void**)&wk, g_wk);
    cudaGetSymbolAddress((void**)&wv, g_wv);
    cudaGetSymbolAddress((void**)&wo, g_wo);

    const int D = DMODEL, L = SEQL, Hh = NHEAD, HD = HEADDIM;
    const long LD = (long)L * D;
    const long LL = (long)L * L;

    // 1) fold LoRA into effective weights (once per launch, graph-capturable)
    {
        int nblk = DEPTH * D * D / 256;
        weff_kernel<<<nblk, 256>>>(Wq, Aq, Bq, wq);
        weff_kernel<<<nblk, 256>>>(Wk, Ak, Bk, wk);
        weff_kernel<<<nblk, 256>>>(Wv, Av, Bv, wv);
        weff_kernel<<<nblk, 256>>>(Wo, Ao, Bo, wo);
    }

    // 2) embedding + phase rotator
    embed_kernel<<<NTOK, 256>>>(idx, tok, pos, phase, x);

    // 3) transformer layers
    for (int i = 0; i < DEPTH; i++) {
        const float* wqi = wq + (long)i * D * D;
        const float* wki = wk + (long)i * D * D;
        const float* wvi = wv + (long)i * D * D;
        const float* woi = wo + (long)i * D * D;

        ln_kernel<<<NTOK, 256>>>(x, ln1w + i * D, ln1b + i * D, h);

        gemm128(h, D, wqi, D, 1, bq + i * D, nullptr, 0, q, D, NTOK, D, D, 0);
        gemm128(h, D, wki, D, 1, bk + i * D, nullptr, 0, k, D, NTOK, D, D, 0);
        gemm128(h, D, wvi, D, 1, bv + i * D, nullptr, 0, v, D, NTOK, D, D, 0);

        // scores[z=b*H+h'][l][j] = q . k  (batched over 32, causal tile-skip)
        gemm128(q, D, k, D, 1, nullptr, nullptr, 0, sc, L,
                L, L, HD, /*flags=*/4,
                BATCH * Hh, Hh,
                LD, HD,          // A offsets (b, h)
                LD, HD,          // B offsets
                (long)Hh * LL, LL);

        softmax_kernel<<<BATCH * Hh * L, 256>>>(sc);

        // o = attn @ V (batched, causal K-limit); B[n,k'] = v[k'*D + n]
        gemm64(sc, L, v, 1, D, nullptr, nullptr, 0, o, D,
               L, HD, L, /*flags=*/8,
               BATCH * Hh, Hh,
               (long)Hh * LL, LL,
               LD, HD,
               LD, HD);

        // x = x + o @ Wo_eff^T + bo
        gemm128(o, D, woi, D, 1, bo + i * D, x, D, x, D, NTOK, D, D, 0);

        ln_kernel<<<NTOK, 256>>>(x, ln2w + i * D, ln2b + i * D, h);

        // ff = gelu(h @ W1^T + b1)
        gemm128(h, D, W1 + (long)i * HIDDEN * D, D, 1, b1 + i * HIDDEN,
                nullptr, 0, ff, HIDDEN, NTOK, HIDDEN, D, /*flags=*/1);
        // x = x + ff @ W2^T + b2
        gemm128(ff, HIDDEN, W2 + (long)i * D * HIDDEN, HIDDEN, 1, b2 + i * D,
                x, D, x, D, NTOK, D, HIDDEN, 0);
    }

    // 4) final LN + LM head
    ln_kernel<<<NTOK, 256>>>(x, lnfw, lnfb, h);
    gemm128(h, D, headW, D, 1, nullptr, nullptr, 0, out, VOCAB,
            NTOK, VOCAB, D, 0);
}

// round 4
// speedup vs baseline: 3.1688x; 3.1688x over previous
#include <cuda_runtime.h>
#include <cuda_bf16.h>
#include <cstdint>
#include <math.h>

// ---------------- Problem constants ----------------
#define VOCAB 32000
#define DMODEL 1024
#define DEPTH 6
#define NHEAD 16
#define SEQL 1024
#define BATCH 2
#define LRANK 16
#define HIDDEN 4096
#define HEADDIM 64
#define NTOK (BATCH * SEQL)          // 2048
#define SCALING 0.5f                  // 8.0 / 16

// ---------------- Scratch (device globals; no allocation allowed) -------------
static __device__ float g_x [NTOK * DMODEL];
static __device__ float g_h [NTOK * DMODEL];
static __device__ float g_q [NTOK * DMODEL];
static __device__ float g_k [NTOK * DMODEL];
static __device__ float g_v [NTOK * DMODEL];
static __device__ float g_o [NTOK * DMODEL];
static __device__ float g_ff[NTOK * HIDDEN];
static __device__ float g_scores[(long)BATCH * NHEAD * SEQL * SEQL]; // 128 MB
static __device__ float g_wq[DEPTH * DMODEL * DMODEL];
static __device__ float g_wk[DEPTH * DMODEL * DMODEL];
static __device__ float g_wv[DEPTH * DMODEL * DMODEL];
static __device__ float g_wo[DEPTH * DMODEL * DMODEL];

// ---------------- small PTX helpers (baseline ISA only, no sm_103a feats) ----
__device__ __forceinline__ uint32_t smem_u32(const void* p) {
    uint32_t a;
    asm("{ .reg .u64 t; cvta.to.shared.u64 t, %1; cvt.u32.u64 %0, t; }"
        : "=r"(a) : "l"(p));
    return a;
}
__device__ __forceinline__ void cp16(uint32_t dst, const void* src) {
    asm volatile("cp.async.cg.shared.global [%0], [%1], 16;"
                 :: "r"(dst), "l"(src));
}
#define CP_COMMIT() asm volatile("cp.async.commit_group;" ::: "memory")
#define CP_WAIT1()  asm volatile("cp.async.wait_group 1;"  ::: "memory")
#define CP_WAIT0()  asm volatile("cp.async.wait_group 0;"  ::: "memory")

__device__ __forceinline__ uint32_t f2tf(float f) {
    uint32_t u;
    asm("cvt.rna.tf32.f32 %0, %1;" : "=r"(u) : "f"(f));
    return u;
}
__device__ __forceinline__ void mma_tf32(float* d, const uint32_t* a,
                                         const uint32_t* b) {
    asm volatile(
        "mma.sync.aligned.m16n8k8.row.col.f32.tf32.tf32.f32 "
        "{%0,%1,%2,%3}, {%4,%5,%6,%7}, {%8,%9}, {%0,%1,%2,%3};"
        : "+f"(d[0]), "+f"(d[1]), "+f"(d[2]), "+f"(d[3])
        : "r"(a[0]), "r"(a[1]), "r"(a[2]), "r"(a[3]), "r"(b[0]), "r"(b[1]));
}

// ---------------- helpers ----------------
__device__ __forceinline__ float gelu_exact(float x) {
    return 0.5f * x * (1.0f + erff(x * 0.70710678118654752440f));
}

// ---------------- W_eff = W + 0.5 * A @ B  (LoRA fold) ----------------
__global__ void weff_kernel(const float* __restrict__ W,
                            const float* __restrict__ Am,   // [DEPTH, D, R]
                            const float* __restrict__ Bm,   // [DEPTH, R, D]
                            float* __restrict__ out) {
    long e = (long)blockIdx.x * 256 + threadIdx.x;
    int layer = (int)(e / (DMODEL * DMODEL));
    int rem   = (int)(e % (DMODEL * DMODEL));
    int orow  = rem / DMODEL;
    int icol  = rem % DMODEL;
    const float* a  = Am + (long)layer * DMODEL * LRANK + (long)orow * LRANK;
    const float* bb = Bm + (long)layer * LRANK * DMODEL + icol;
    float s = 0.0f;
#pragma unroll
    for (int r = 0; r < LRANK; r++) s += a[r] * bb[(long)r * DMODEL];
    out[e] = W[e] + SCALING * s;
}

// ---------------- Embedding + phase rotator ----------------
__global__ void embed_kernel(const int* __restrict__ idx,
                             const float* __restrict__ tok,
                             const float* __restrict__ pos,
                             const float* __restrict__ phase,
                             float* __restrict__ x) {
    int row = blockIdx.x;
    int l   = row % SEQL;
    int t   = idx[row];
    for (int d = threadIdx.x; d < DMODEL; d += blockDim.x) {
        float phi = tanhf(phase[d]) * 3.14159265358979323846f;
        float fac = cosf(phi) - sinf(phi);
        x[(long)row * DMODEL + d] =
            (tok[(long)t * DMODEL + d] + pos[(long)l * DMODEL + d]) * fac;
    }
}

// ---------------- LayerNorm ----------------
__global__ void ln_kernel(const float* __restrict__ x,
                          const float* __restrict__ w,
                          const float* __restrict__ b,
                          float* __restrict__ o) {
    int row = blockIdx.x;
    const float* xr = x + (long)row * DMODEL;
    int tid = threadIdx.x;
    float s = 0.f, s2 = 0.f;
    float v[4];
#pragma unroll
    for (int j = 0; j < 4; j++) {
        v[j] = xr[tid + 256 * j];
        s += v[j]; s2 += v[j] * v[j];
    }
    __shared__ float r1[256], r2[256];
    r1[tid] = s; r2[tid] = s2;
    __syncthreads();
    for (int off = 128; off > 0; off >>= 1) {
        if (tid < off) { r1[tid] += r1[tid + off]; r2[tid] += r2[tid + off]; }
        __syncthreads();
    }
    float mean = r1[0] * (1.0f / DMODEL);
    float var  = r2[0] * (1.0f / DMODEL) - mean * mean;
    float rstd = rsqrtf(var + 1e-5f);
    float* orow = o + (long)row * DMODEL;
#pragma unroll
    for (int j = 0; j < 4; j++) {
        int d = tid + 256 * j;
        orow[d] = (v[j] - mean) * rstd * w[d] + b[d];
    }
}

// ---------------- Causal softmax ----------------
__global__ void softmax_kernel(float* __restrict__ sc) {
    long row = blockIdx.x;
    int l = (int)(row % SEQL);
    float* s = sc + row * (long)SEQL;
    int tid = threadIdx.x;
    __shared__ float red[256];

    const float scale = 0.125f;   // HEADDIM^-0.5
    float mx = -3.4e38f;
    for (int j = tid; j <= l; j += 256) mx = fmaxf(mx, s[j]);
    red[tid] = mx;
    __syncthreads();
    for (int off = 128; off > 0; off >>= 1) {
        if (tid < off) red[tid] = fmaxf(red[tid], red[tid + off]);
        __syncthreads();
    }
    mx = red[0] * scale;
    __syncthreads();

    float sum = 0.f;
    for (int j = tid; j <= l; j += 256) {
        float e = __expf(s[j] * scale - mx);
        s[j] = e;
        sum += e;
    }
    red[tid] = sum;
    __syncthreads();
    for (int off = 128; off > 0; off >>= 1) {
        if (tid < off) red[tid] += red[tid + off];
        __syncthreads();
    }
    float inv = 1.0f / red[0];
    for (int j = tid; j <= l; j += 256) s[j] *= inv;
    for (int j = l + 1 + tid; j < SEQL; j += 256) s[j] = 0.0f;
}

// ---------------- tf32 mma.sync GEMM ----------------
// C[m,n] = sum_k A[m*lda+k] * B[n*sBn + k*sBk]  (+bias)(gelu)(+residual)
// flags: 1 = gelu, 4 = causal tile-skip (scores), 8 = causal K-limit (attn@V)
// BM=128, BK=32; 8 warps in 2x4, warp tile 64 x (BN/4).
template<int BN>
__global__ __launch_bounds__(256)
void mma_gemm(const float* __restrict__ A, int lda,
              const float* __restrict__ Bp, long sBn, long sBk,
              const float* __restrict__ bias,
              const float* __restrict__ res, int ldr,
              float* __restrict__ C, int ldc,
              int K, int flags, int batchH,
              long aO, long aI, long bO, long bI, long cO, long cI) {
    constexpr int BM = 128, BK = 32, LDSS = BK + 4;       // 36 floats/row
    extern __shared__ float smf[];
    float* As = smf;                                       // [2][BM][36]
    float* Bs = smf + 2 * BM * LDSS;                       // [2][BN][36]

    if (batchH > 0) {
        int z = blockIdx.z;
        A  += (z / batchH) * aO + (z % batchH) * aI;
        Bp += (z / batchH) * bO + (z % batchH) * bI;
        C  += (z / batchH) * cO + (z % batchH) * cI;
    }
    const int bm0 = blockIdx.y * BM;
    const int bn0 = blockIdx.x * BN;
    if (flags & 4) { if (bn0 > bm0 + BM - 1) return; }
    int Keff = K;
    if (flags & 8) Keff = min(K, bm0 + BM);
    const int T = Keff / BK;

    const int tid  = threadIdx.x;
    const int w    = tid >> 5;
    const int lane = tid & 31;
    const int wm = w >> 2, wn = w & 3;
    const int g = lane >> 2, tig = lane & 3;
    constexpr int WN = BN / 4;
    constexpr int NT = WN / 8;            // n-tiles per warp (4 or 2)

    float acc[4][NT][4];
#pragma unroll
    for (int i = 0; i < 4; i++)
#pragma unroll
        for (int j = 0; j < NT; j++)
#pragma unroll
            for (int r = 0; r < 4; r++) acc[i][j][r] = 0.0f;

    const bool bK = (sBk == 1);

    // tile loaders -------------------------------------------------------
    auto load_tile = [&](int it, int buf) {
        const int k0 = it * BK;
        // A: 128x32, k-contiguous; 4 float4 per thread via cp.async
#pragma unroll
        for (int t = 0; t < 4; t++) {
            int vv = tid + t * 256;
            int m = vv >> 3, kq = vv & 7;
            cp16(smem_u32(&As[buf * BM * LDSS + m * LDSS + kq * 4]),
                 A + (long)(bm0 + m) * lda + k0 + kq * 4);
        }
        if (bK) {
#pragma unroll
            for (int t = 0; t < BN / 32; t++) {
                int vv = tid + t * 256;
                int n = vv >> 3, kq = vv & 7;
                cp16(smem_u32(&Bs[buf * BN * LDSS + n * LDSS + kq * 4]),
                     Bp + (long)(bn0 + n) * sBn + k0 + kq * 4);
            }
        } else {
            // n-contiguous source: element (n, kk) = Bp[(k0+kk)*sBk + bn0+n]
#pragma unroll
            for (int t = 0; t < BN / 32; t++) {
                int vv = tid + t * 256;
                int kk = vv / (BN / 4), nq = vv % (BN / 4);
                float4 f = *reinterpret_cast<const float4*>(
                    Bp + (long)(k0 + kk) * sBk + bn0 + nq * 4);
                float* bb = &Bs[buf * BN * LDSS + (nq * 4) * LDSS + kk];
                bb[0 * LDSS] = f.x;
                bb[1 * LDSS] = f.y;
                bb[2 * LDSS] = f.z;
                bb[3 * LDSS] = f.w;
            }
        }
    };

    load_tile(0, 0);
    CP_COMMIT();

    for (int it = 0; it < T; it++) {
        const int buf = it & 1;
        if (it + 1 < T) {
            load_tile(it + 1, buf ^ 1);
            CP_COMMIT();
            CP_WAIT1();
        } else {
            CP_WAIT0();
        }
        __syncthreads();

        const float* Ab = As + buf * BM * LDSS;
        const float* Bb = Bs + buf * BN * LDSS;

#pragma unroll
        for (int ks = 0; ks < 4; ks++) {
            uint32_t af[4][4];
#pragma unroll
            for (int i = 0; i < 4; i++) {
                const float* ap = Ab + (wm * 64 + i * 16) * LDSS + ks * 8;
                af[i][0] = f2tf(ap[g * LDSS + tig]);
                af[i][1] = f2tf(ap[(g + 8) * LDSS + tig]);
                af[i][2] = f2tf(ap[g * LDSS + tig + 4]);
                af[i][3] = f2tf(ap[(g + 8) * LDSS + tig + 4]);
            }
            uint32_t bf[NT][2];
#pragma unroll
            for (int j = 0; j < NT; j++) {
                const float* bp = Bb + (wn * WN + j * 8 + g) * LDSS + ks * 8;
                bf[j][0] = f2tf(bp[tig]);
                bf[j][1] = f2tf(bp[tig + 4]);
            }
#pragma unroll
            for (int i = 0; i < 4; i++)
#pragma unroll
                for (int j = 0; j < NT; j++)
                    mma_tf32(acc[i][j], af[i], bf[j]);
        }
        __syncthreads();
    }

    // epilogue -----------------------------------------------------------
#pragma unroll
    for (int i = 0; i < 4; i++) {
        int r0 = bm0 + wm * 64 + i * 16 + g;
#pragma unroll
        for (int j = 0; j < NT; j++) {
            int c = bn0 + wn * WN + j * 8 + tig * 2;
            float e00 = acc[i][j][0], e01 = acc[i][j][1];
            float e10 = acc[i][j][2], e11 = acc[i][j][3];
            if (bias) {
                float2 bb = *reinterpret_cast<const float2*>(bias + c);
                e00 += bb.x; e01 += bb.y; e10 += bb.x; e11 += bb.y;
            }
            if (flags & 1) {
                e00 = gelu_exact(e00); e01 = gelu_exact(e01);
                e10 = gelu_exact(e10); e11 = gelu_exact(e11);
            }
            if (res) {
                float2 ra = *reinterpret_cast<const float2*>(
                    res + (long)r0 * ldr + c);
                float2 rb = *reinterpret_cast<const float2*>(
                    res + (long)(r0 + 8) * ldr + c);
                e00 += ra.x; e01 += ra.y; e10 += rb.x; e11 += rb.y;
            }
            *reinterpret_cast<float2*>(C + (long)r0 * ldc + c) =
                make_float2(e00, e01);
            *reinterpret_cast<float2*>(C + (long)(r0 + 8) * ldc + c) =
                make_float2(e10, e11);
        }
    }
}

// ---------------- host-side launch helpers ----------------
static constexpr int SMEM128 = (2 * 128 * 36 + 2 * 128 * 36) * 4;  // 73728
static constexpr int SMEM64  = (2 * 128 * 36 + 2 * 64  * 36) * 4;  // 55296

static void tgemm128(const float* A, int lda, const float* B, long sBn, long sBk,
                     const float* bias, const float* res, int ldr,
                     float* C, int ldc, int M, int N, int K, int flags,
                     int batch = 1, int batchH = 0,
                     long aO = 0, long aI = 0, long bO = 0, long bI = 0,
                     long cO = 0, long cI = 0) {
    dim3 gdim(N / 128, M / 128, batch);
    mma_gemm<128><<<gdim, 256, SMEM128>>>(A, lda, B, sBn, sBk, bias, res, ldr,
                                          C, ldc, K, flags, batchH,
                                          aO, aI, bO, bI, cO, cI);
}
static void tgemm64(const float* A, int lda, const float* B, long sBn, long sBk,
                    const float* bias, const float* res, int ldr,
                    float* C, int ldc, int M, int N, int K, int flags,
                    int batch = 1, int batchH = 0,
                    long aO = 0, long aI = 0, long bO = 0, long bI = 0,
                    long cO = 0, long cI = 0) {
    dim3 gdim(N / 64, M / 128, batch);
    mma_gemm<64><<<gdim, 256, SMEM64>>>(A, lda, B, sBn, sBk, bias, res, ldr,
                                        C, ldc, K, flags, batchH,
                                        aO, aI, bO, bI, cO, cI);
}

// ---------------- entry point ----------------
extern "C" void kernel_launch(void* const* d_in, const int* in_sizes, int n_in,
                              void* d_out, int out_size) {
    // dict order: 0 idx, 1 tok, 2 pos, 3 phase, 4 ln1_w, 5 ln1_b, 6 ln2_w, 7 ln2_b,
    // 8..23 {W,b,B,A} x {q,k,v,o}, 24 W1, 25 b1, 26 W2, 27 b2, 28 lnf_w, 29 lnf_b, 30 head_W
    const int*   idx   = (const int*)  d_in[0];
    const float* tok   = (const float*)d_in[1];
    const float* pos   = (const float*)d_in[2];
    const float* phase = (const float*)d_in[3];
    const float* ln1w  = (const float*)d_in[4];
    const float* ln1b  = (const float*)d_in[5];

    const float *ln2w, *ln2b;
    int wbase;
    if (in_sizes[6] == DEPTH * DMODEL) {        // dict order
        ln2w = (const float*)d_in[6];
        ln2b = (const float*)d_in[7];
        wbase = 8;
    } else {                                     // signature order fallback
        ln2w = (const float*)d_in[22];
        ln2b = (const float*)d_in[23];
        wbase = 6;
    }
    const float* Wq = (const float*)d_in[wbase + 0];
    const float* bq = (const float*)d_in[wbase + 1];
    const float* Bq = (const float*)d_in[wbase + 2];
    const float* Aq = (const float*)d_in[wbase + 3];
    const float* Wk = (const float*)d_in[wbase + 4];
    const float* bk = (const float*)d_in[wbase + 5];
    const float* Bk = (const float*)d_in[wbase + 6];
    const float* Ak = (const float*)d_in[wbase + 7];
    const float* Wv = (const float*)d_in[wbase + 8];
    const float* bv = (const float*)d_in[wbase + 9];
    const float* Bv = (const float*)d_in[wbase + 10];
    const float* Av = (const float*)d_in[wbase + 11];
    const float* Wo = (const float*)d_in[wbase + 12];
    const float* bo = (const float*)d_in[wbase + 13];
    const float* Bo = (const float*)d_in[wbase + 14];
    const float* Ao = (const float*)d_in[wbase + 15];
    const float* W1 = (const float*)d_in[24];
    const float* b1 = (const float*)d_in[25];
    const float* W2 = (const float*)d_in[26];
    const float* b2 = (const float*)d_in[27];
    const float* lnfw = (const float*)d_in[28];
    const float* lnfb = (const float*)d_in[29];
    const float* headW = (const float*)d_in[30];
    float* out = (float*)d_out;

    float *x, *h, *q, *k, *v, *o, *ff, *sc, *wq, *wk, *wv, *wo;
    cudaGetSymbolAddress((void**)&x,  g_x);
    cudaGetSymbolAddress((void**)&h,  g_h);
    cudaGetSymbolAddress((void**)&q,  g_q);
    cudaGetSymbolAddress((void**)&k,  g_k);
    cudaGetSymbolAddress((void**)&v,  g_v);
    cudaGetSymbolAddress((void**)&o,  g_o);
    cudaGetSymbolAddress((void**)&ff, g_ff);
    cudaGetSymbolAddress((void**)&sc, g_scores);
    cudaGetSymbolAddress((void**)&wq, g_wq);
    cudaGetSymbolAddress((void**)&wk, g_wk);
    cudaGetSymbolAddress((void**)&wv, g_wv);
    cudaGetSymbolAddress((void**)&wo, g_wo);

    cudaFuncSetAttribute(mma_gemm<128>,
                         cudaFuncAttributeMaxDynamicSharedMemorySize, SMEM128);
    cudaFuncSetAttribute(mma_gemm<64>,
                         cudaFuncAttributeMaxDynamicSharedMemorySize, SMEM64);

    const int D = DMODEL, L = SEQL, Hh = NHEAD, HD = HEADDIM;
    const long LD = (long)L * D;
    const long LL = (long)L * L;

    // 1) fold LoRA into effective weights
    {
        int nblk = DEPTH * D * D / 256;
        weff_kernel<<<nblk, 256>>>(Wq, Aq, Bq, wq);
        weff_kernel<<<nblk, 256>>>(Wk, Ak, Bk, wk);
        weff_kernel<<<nblk, 256>>>(Wv, Av, Bv, wv);
        weff_kernel<<<nblk, 256>>>(Wo, Ao, Bo, wo);
    }

    // 2) embedding + phase rotator
    embed_kernel<<<NTOK, 256>>>(idx, tok, pos, phase, x);

    // 3) transformer layers
    for (int i = 0; i < DEPTH; i++) {
        const float* wqi = wq + (long)i * D * D;
        const float* wki = wk + (long)i * D * D;
        const float* wvi = wv + (long)i * D * D;
        const float* woi = wo + (long)i * D * D;

        ln_kernel<<<NTOK, 256>>>(x, ln1w + i * D, ln1b + i * D, h);

        tgemm128(h, D, wqi, D, 1, bq + i * D, nullptr, 0, q, D, NTOK, D, D, 0);
        tgemm128(h, D, wki, D, 1, bk + i * D, nullptr, 0, k, D, NTOK, D, D, 0);
        tgemm128(h, D, wvi, D, 1, bv + i * D, nullptr, 0, v, D, NTOK, D, D, 0);

        // scores[z][l][j] = q . k  (batched over B*H, causal tile-skip)
        tgemm128(q, D, k, D, 1, nullptr, nullptr, 0, sc, L,
                 L, L, HD, /*flags=*/4,
                 BATCH * Hh, Hh,
                 LD, HD, LD, HD,
                 (long)Hh * LL, LL);

        softmax_kernel<<<BATCH * Hh * L, 256>>>(sc);

        // o = attn @ V (batched, causal K-limit); B element (n,k') = v[k'*D + n]
        tgemm64(sc, L, v, 1, D, nullptr, nullptr, 0, o, D,
                L, HD, L, /*flags=*/8,
                BATCH * Hh, Hh,
                (long)Hh * LL, LL,
                LD, HD,
                LD, HD);

        // x = x + o @ Wo_eff^T + bo
        tgemm128(o, D, woi, D, 1, bo + i * D, x, D, x, D, NTOK, D, D, 0);

        ln_kernel<<<NTOK, 256>>>(x, ln2w + i * D, ln2b + i * D, h);

        // ff = gelu(h @ W1^T + b1)
        tgemm128(h, D, W1 + (long)i * HIDDEN * D, D, 1, b1 + i * HIDDEN,
                 nullptr, 0, ff, HIDDEN, NTOK, HIDDEN, D, /*flags=*/1);
        // x = x + ff @ W2^T + b2
        tgemm128(ff, HIDDEN, W2 + (long)i * D * HIDDEN, HIDDEN, 1, b2 + i * D,
                 x, D, x, D, NTOK, D, HIDDEN, 0);
    }

    // 4) final LN + LM head
    ln_kernel<<<NTOK, 256>>>(x, lnfw, lnfb, h);
    tgemm128(h, D, headW, D, 1, nullptr, nullptr, 0, out, VOCAB,
             NTOK, VOCAB, D, 0);
}